// round 13
// baseline (speedup 1.0000x reference)
#include <cuda_runtime.h>
#include <cstdint>

// TinyLSTM: B=64, T=2048, H=256, V=256
// out = [ logits (64*2048*256) | h_n (64*256) | c_n (64*256) ]  (float32)

#define T_SEQ 2048
#define BATCH 64
#define HID   256
#define G4    1024
#define VOCAB 256
#define LOGITS_ELEMS (BATCH * T_SEQ * HID)

#define CH 36           // skewed k-chunk stride (floats)
#define N_TILES 4096u   // 64 t-chunks x 64 batches (32 rows each)

// scratch (static device arrays; no allocation)
__device__ float g_xtab[VOCAB * G4];   // [v][r] = W_ih[r][v] + b_ih[r] + b_hh[r]
__device__ float g_fcwt[HID * VOCAB];  // [k][c] = fc_W[c][k]
__device__ unsigned int g_bar[16];     // per-group counters (64 warp-arrivals/step)
__device__ unsigned int g_ticket;      // FC tile ticket counter

// ---- packed f32x2 helpers ----
__device__ __forceinline__ unsigned long long pk2(float a, float b) {
    unsigned long long r;
    asm("mov.b64 %0, {%1, %2};" : "=l"(r) : "f"(a), "f"(b));
    return r;
}
__device__ __forceinline__ void upk2(unsigned long long v, float& a, float& b) {
    asm("mov.b64 {%0, %1}, %2;" : "=f"(a), "=f"(b) : "l"(v));
}
__device__ __forceinline__ void ffma2(unsigned long long& d, unsigned long long a, unsigned long long b) {
    asm("fma.rn.f32x2 %0, %1, %2, %0;" : "+l"(d) : "l"(a), "l"(b));
}
__device__ __forceinline__ float4 ldcg4(const float* p) {
    float4 v;
    asm volatile("ld.global.cg.v4.f32 {%0,%1,%2,%3}, [%4];"
                 : "=f"(v.x), "=f"(v.y), "=f"(v.z), "=f"(v.w) : "l"(p));
    return v;
}
__device__ __forceinline__ void red_release_add(unsigned int* p, unsigned int v) {
    asm volatile("red.release.gpu.global.add.u32 [%0], %1;" :: "l"(p), "r"(v) : "memory");
}
__device__ __forceinline__ unsigned int ld_acquire(const unsigned int* p) {
    unsigned int v;
    asm volatile("ld.acquire.gpu.global.u32 %0, [%1];" : "=r"(v) : "l"(p) : "memory");
    return v;
}

// =====================================================================
// Phase 0: token table (biases folded), fc_W transpose, reset counters
// =====================================================================
__global__ void prep_kernel(const float* __restrict__ W_ih,
                            const float* __restrict__ b_ih,
                            const float* __restrict__ b_hh,
                            const float* __restrict__ fc_W) {
    int idx = blockIdx.x * blockDim.x + threadIdx.x;
    if (idx < VOCAB * G4) {
        int v = idx >> 10;
        int r = idx & 1023;
        g_xtab[v * G4 + r] = W_ih[r * VOCAB + v] + b_ih[r] + b_hh[r];
    }
    if (idx < HID * VOCAB) {
        int k = idx >> 8;
        int c = idx & 255;
        g_fcwt[k * VOCAB + c] = fc_W[c * HID + k];
    }
    if (idx < 16) g_bar[idx] = 0u;
    if (idx == 16) g_ticket = 0u;
}

// =====================================================================
// Shared-memory union: LSTM view (ping-pong h) / FC-tile view (< 48 KB)
// =====================================================================
#define FC_WPAD 260
union SMemU {
    struct {
        float sh_h[2][4][8 * CH];  // ping-pong h(t-1): [buf][batch][chunk*CH+j]
        int   sh_tok[2][4];        // double-buffered tokens
    } l;
    struct {
        float w[32][FC_WPAD];      // weight k-slab  (~33 KB)
        float h[32][33];           // h rows k-slab  (~4.2 KB)
    } f;
};

// =====================================================================
// FC tile: 32 rows x 256 cols, 256 threads, 4x8 register tile, f32x2.
// =====================================================================
__device__ __forceinline__ void fc_tile(float* __restrict__ sw,
                                        float* __restrict__ shh,
                                        float* __restrict__ out,
                                        const float* __restrict__ fc_b,
                                        size_t row_base, int tid) {
    const int rg = tid >> 5;
    const int cg = tid & 31;

    unsigned long long acc[4][4];
#pragma unroll
    for (int a = 0; a < 4; a++)
#pragma unroll
        for (int b = 0; b < 4; b++) acc[a][b] = 0ull;

    for (int k0 = 0; k0 < HID; k0 += 32) {
        __syncthreads();              // also joins the tid0 dependency spin
        for (int i = tid; i < 32 * 64; i += 256) {
            int kk = i >> 6, c4 = i & 63;
            *reinterpret_cast<float4*>(&sw[kk * FC_WPAD + c4 * 4]) =
                *reinterpret_cast<const float4*>(&g_fcwt[(size_t)(k0 + kk) * VOCAB + c4 * 4]);
        }
        {
            int rr = tid >> 3, k4 = tid & 7;
            float4 v = *reinterpret_cast<const float4*>(
                &out[(row_base + rr) * HID + k0 + k4 * 4]);
            shh[rr * 33 + k4 * 4 + 0] = v.x;
            shh[rr * 33 + k4 * 4 + 1] = v.y;
            shh[rr * 33 + k4 * 4 + 2] = v.z;
            shh[rr * 33 + k4 * 4 + 3] = v.w;
        }
        __syncthreads();
#pragma unroll 4
        for (int kk = 0; kk < 32; kk++) {
            ulonglong2 wv0 = *reinterpret_cast<const ulonglong2*>(&sw[kk * FC_WPAD + cg * 8]);
            ulonglong2 wv1 = *reinterpret_cast<const ulonglong2*>(&sw[kk * FC_WPAD + cg * 8 + 4]);
#pragma unroll
            for (int rr = 0; rr < 4; rr++) {
                float hv = shh[(rg * 4 + rr) * 33 + kk];
                unsigned long long hp = pk2(hv, hv);
                ffma2(acc[rr][0], hp, wv0.x);
                ffma2(acc[rr][1], hp, wv0.y);
                ffma2(acc[rr][2], hp, wv1.x);
                ffma2(acc[rr][3], hp, wv1.y);
            }
        }
    }

    float bias[8];
#pragma unroll
    for (int cc = 0; cc < 8; cc++) bias[cc] = __ldg(&fc_b[cg * 8 + cc]);
#pragma unroll
    for (int rr = 0; rr < 4; rr++) {
        float v[8];
        upk2(acc[rr][0], v[0], v[1]);
        upk2(acc[rr][1], v[2], v[3]);
        upk2(acc[rr][2], v[4], v[5]);
        upk2(acc[rr][3], v[6], v[7]);
        float4 o0 = make_float4(v[0] + bias[0], v[1] + bias[1], v[2] + bias[2], v[3] + bias[3]);
        float4 o1 = make_float4(v[4] + bias[4], v[5] + bias[5], v[6] + bias[6], v[7] + bias[7]);
        float* dst = out + (row_base + rg * 4 + rr) * VOCAB + cg * 8;
        *reinterpret_cast<float4*>(dst)     = o0;
        *reinterpret_cast<float4*>(dst + 4) = o1;
    }
}

// =====================================================================
// Fused kernel, grid 148. CTA 0..127: persistent LSTM then FC pool;
// CTA 128..147: FC workers from t=0.
// LSTM step (warp-decoupled): per-warp acquire-poll -> stage share into
// ping-pong smem -> ONE bar.sync -> matmul/reduce/epilogue -> h STG ->
// __syncwarp -> lane0 red.release (64 warp-arrivals per step).
// Ping-pong makes one bar sufficient: a warp reaches stage(t+2) only
// after all 64 warps released t+1, so buffer reuse is race-free.
// =====================================================================
__global__ void __launch_bounds__(256, 1)
fused_kernel(const int* __restrict__ x,
             const float* __restrict__ W_hh,
             float* __restrict__ out,
             const float* __restrict__ fc_b) {
    __shared__ SMemU sm;
    __shared__ unsigned sh_tix;

    const int cta = blockIdx.x;
    const int tid = threadIdx.x;
    float* hsout = out;                                 // [B][T][H]

    if (cta < 128) {
        // ================= LSTM phase =================
        const int gb     = cta >> 3;       // batch group 0..15
        const int m      = cta & 7;        // gate-slice member 0..7
        const int b_base = gb * 4;
        const int j_base = m * 32;

        const int j    = tid >> 3;         // local column 0..31
        const int kq   = tid & 7;          // k-chunk 0..7 (32 k each)
        const int bmy  = kq >> 1;          // epilogue batch owned by this thread
        const int row0 = j_base + j;       // gate-0 row; gate g at row0 + g*256
        const int lane = tid & 31;

        unsigned long long w2[64];
#pragma unroll
        for (int g = 0; g < 4; g++) {
            const float4* wr = reinterpret_cast<const float4*>(
                W_hh + (size_t)(g * 256 + row0) * HID + kq * 32);
#pragma unroll
            for (int i = 0; i < 8; i++) {
                float4 v = wr[i];
                w2[g * 16 + 2 * i]     = pk2(v.x, v.y);
                w2[g * 16 + 2 * i + 1] = pk2(v.z, v.w);
            }
        }
        float creg = 0.0f;
        if (tid < 4) sm.l.sh_tok[0][tid] = x[(size_t)(b_base + tid) * T_SEQ + 0] & 255;

        float* hN = out + (size_t)LOGITS_ELEMS;
        float* cN = hN + BATCH * HID;
        unsigned int* bar = &g_bar[gb];

        for (int t = 0; t < T_SEQ; t++) {
            const int pb = t & 1;

            // ---- per-warp wait for h(t-1) published by all 64 warps ----
            if (t > 0) {
                if (lane == 0) {
                    const unsigned tgt = 64u * (unsigned)t;
                    while (ld_acquire(bar) < tgt) { }
                }
                __syncwarp();
            }

            // ---- stage this warp's share into ping-pong smem ----
            {
                int bb = tid >> 6, k4 = tid & 63;
                float4 hv;
                if (t == 0) {
                    hv = make_float4(0.f, 0.f, 0.f, 0.f);
                } else {
                    hv = ldcg4(&hsout[((size_t)(b_base + bb) * T_SEQ + (t - 1)) * HID + k4 * 4]);
                }
                *reinterpret_cast<float4*>(
                    &sm.l.sh_h[pb][bb][(k4 >> 3) * CH + (k4 & 7) * 4]) = hv;
            }
            if (tid < 4 && t + 1 < T_SEQ)
                sm.l.sh_tok[pb ^ 1][tid] = x[(size_t)(b_base + tid) * T_SEQ + t + 1] & 255;

            // ---- token-table contributions (overlap the bar wait) ----
            const int tok = sm.l.sh_tok[pb][bmy];   // written before bar(t-1)
            float xg[4];
#pragma unroll
            for (int g = 0; g < 4; g++)
                xg[g] = __ldg(&g_xtab[tok * G4 + g * 256 + row0]);

            __syncthreads();                        // the ONE bar per step

            // ---- matmul: 4 gates x 4 batches x 32 k, weights in regs ----
            unsigned long long acc2[4][4];
#pragma unroll
            for (int g = 0; g < 4; g++)
#pragma unroll
                for (int b = 0; b < 4; b++) acc2[g][b] = 0ull;
#pragma unroll
            for (int b = 0; b < 4; b++) {
                const ulonglong2* hp =
                    reinterpret_cast<const ulonglong2*>(&sm.l.sh_h[pb][b][kq * CH]);
#pragma unroll
                for (int i = 0; i < 8; i++) {
                    ulonglong2 hv = hp[i];
#pragma unroll
                    for (int g = 0; g < 4; g++) {
                        ffma2(acc2[g][b], w2[g * 16 + 2 * i],     hv.x);
                        ffma2(acc2[g][b], w2[g * 16 + 2 * i + 1], hv.y);
                    }
                }
            }

            // ---- horizontal sums ----
            float af[4][4];
#pragma unroll
            for (int g = 0; g < 4; g++)
#pragma unroll
                for (int b = 0; b < 4; b++) {
                    float a0, a1;
                    upk2(acc2[g][b], a0, a1);
                    af[g][b] = a0 + a1;
                }

            // ---- reduce-scatter over the 8 k-chunks ----
            const bool lo = (kq < 4);
            float a2[4][2];
#pragma unroll
            for (int g = 0; g < 4; g++) {
                float s0 = lo ? af[g][2] : af[g][0];
                float s1 = lo ? af[g][3] : af[g][1];
                s0 = __shfl_xor_sync(0xffffffffu, s0, 4);
                s1 = __shfl_xor_sync(0xffffffffu, s1, 4);
                a2[g][0] = (lo ? af[g][0] : af[g][2]) + s0;
                a2[g][1] = (lo ? af[g][1] : af[g][3]) + s1;
            }
            const bool sel = (kq & 2);
            float fin[4];
#pragma unroll
            for (int g = 0; g < 4; g++) {
                float s = sel ? a2[g][0] : a2[g][1];
                s = __shfl_xor_sync(0xffffffffu, s, 2);
                fin[g] = (sel ? a2[g][1] : a2[g][0]) + s;
            }
#pragma unroll
            for (int g = 0; g < 4; g++)
                fin[g] += __shfl_xor_sync(0xffffffffu, fin[g], 1);

            // ---- epilogue inline (pair-redundant; odd lane stores) ----
            {
                float iv = fin[0] + xg[0];
                float fv = fin[1] + xg[1];
                float gv = fin[2] + xg[2];
                float ov = fin[3] + xg[3];
                float is = __fdividef(1.f, 1.f + __expf(-iv));
                float fs = __fdividef(1.f, 1.f + __expf(-fv));
                float gt = 1.f - __fdividef(2.f, 1.f + __expf(2.f * gv));
                float os = __fdividef(1.f, 1.f + __expf(-ov));
                creg = fs * creg + is * gt;
                float ct = 1.f - __fdividef(2.f, 1.f + __expf(2.f * creg));
                float hv = os * ct;
                if (kq & 1) {
                    hsout[((size_t)(b_base + bmy) * T_SEQ + t) * HID + row0] = hv;
                    if (t == T_SEQ - 1) {
                        hN[(b_base + bmy) * HID + row0] = hv;
                        cN[(b_base + bmy) * HID + row0] = creg;
                    }
                }
            }

            // ---- per-warp publish: syncwarp orders all lanes' STGs ----
            __syncwarp();
            if (lane == 0) red_release_add(bar, 1u);
        }
    }

    // ================= FC worker pool (all 148 CTAs end up here) =========
    for (;;) {
        __syncthreads();                       // protect sh_tix + smem reuse
        if (tid == 0) sh_tix = atomicAdd(&g_ticket, 1u);
        __syncthreads();
        unsigned tix = sh_tix;
        if (tix >= N_TILES) break;
        int tc = (int)(tix >> 6);              // t-chunk 0..63 (time-major order)
        int b  = (int)(tix & 63u);             // batch 0..63
        // WAR-safe dep: counter >= 64*(32tc+33) means staging of step
        // 32tc+32 is complete -> row 32tc+31 already consumed.
        unsigned need = 64u * (32u * (unsigned)tc + 33u);
        const unsigned cap = 64u * (unsigned)T_SEQ;
        if (need > cap) need = cap;
        if (tid == 0) {
            while (ld_acquire(&g_bar[b >> 2]) < need) { }
        }
        fc_tile(&sm.f.w[0][0], &sm.f.h[0][0], out, fc_b,
                (size_t)b * T_SEQ + (size_t)(32 * tc), tid);
    }
}

// =====================================================================
extern "C" void kernel_launch(void* const* d_in, const int* in_sizes, int n_in,
                              void* d_out, int out_size) {
    (void)in_sizes; (void)n_in; (void)out_size;
    const int*   x      = (const int*)d_in[0];     // int32 tokens
    const float* W_ih   = (const float*)d_in[1];
    const float* W_hh   = (const float*)d_in[2];
    const float* b_ih   = (const float*)d_in[3];
    const float* b_hh   = (const float*)d_in[4];
    const float* fc_W   = (const float*)d_in[5];
    const float* fc_b   = (const float*)d_in[6];
    float* out = (float*)d_out;

    prep_kernel<<<1024, 256>>>(W_ih, b_ih, b_hh, fc_W);
    fused_kernel<<<148, 256>>>(x, W_hh, out, fc_b);
}

// round 14
// speedup vs baseline: 1.2901x; 1.2901x over previous
#include <cuda_runtime.h>
#include <cstdint>

// TinyLSTM: B=64, T=2048, H=256, V=256
// out = [ logits (64*2048*256) | h_n (64*256) | c_n (64*256) ]  (float32)

#define T_SEQ 2048
#define BATCH 64
#define HID   256
#define G4    1024
#define VOCAB 256
#define LOGITS_ELEMS (BATCH * T_SEQ * HID)

#define CH 36           // skewed k-chunk stride (floats)
#define N_TILES 4096u   // 64 t-chunks x 64 batches (32 rows each)
#define BAR_STRIDE 64   // 64 uints = 256 B: one counter per L2 line-pair (slice spread)

// scratch (static device arrays; no allocation)
__device__ float g_xtab[VOCAB * G4];   // [v][r] = W_ih[r][v] + b_ih[r] + b_hh[r]
__device__ float g_fcwt[HID * VOCAB];  // [k][c] = fc_W[c][k]
__device__ __align__(256) unsigned int g_bar[16 * BAR_STRIDE];  // padded counters
__device__ __align__(256) unsigned int g_ticket[BAR_STRIDE];    // own line

// ---- packed f32x2 helpers ----
__device__ __forceinline__ unsigned long long pk2(float a, float b) {
    unsigned long long r;
    asm("mov.b64 %0, {%1, %2};" : "=l"(r) : "f"(a), "f"(b));
    return r;
}
__device__ __forceinline__ void upk2(unsigned long long v, float& a, float& b) {
    asm("mov.b64 {%0, %1}, %2;" : "=f"(a), "=f"(b) : "l"(v));
}
__device__ __forceinline__ void ffma2(unsigned long long& d, unsigned long long a, unsigned long long b) {
    asm("fma.rn.f32x2 %0, %1, %2, %0;" : "+l"(d) : "l"(a), "l"(b));
}
__device__ __forceinline__ float4 ldcg4(const float* p) {
    float4 v;
    asm volatile("ld.global.cg.v4.f32 {%0,%1,%2,%3}, [%4];"
                 : "=f"(v.x), "=f"(v.y), "=f"(v.z), "=f"(v.w) : "l"(p));
    return v;
}
__device__ __forceinline__ void red_release_add(unsigned int* p, unsigned int v) {
    asm volatile("red.release.gpu.global.add.u32 [%0], %1;" :: "l"(p), "r"(v) : "memory");
}
__device__ __forceinline__ unsigned int ld_acquire(const unsigned int* p) {
    unsigned int v;
    asm volatile("ld.acquire.gpu.global.u32 %0, [%1];" : "=r"(v) : "l"(p) : "memory");
    return v;
}

// =====================================================================
// Phase 0: token table (biases folded), fc_W transpose, reset counters
// =====================================================================
__global__ void prep_kernel(const float* __restrict__ W_ih,
                            const float* __restrict__ b_ih,
                            const float* __restrict__ b_hh,
                            const float* __restrict__ fc_W) {
    int idx = blockIdx.x * blockDim.x + threadIdx.x;
    if (idx < VOCAB * G4) {
        int v = idx >> 10;
        int r = idx & 1023;
        g_xtab[v * G4 + r] = W_ih[r * VOCAB + v] + b_ih[r] + b_hh[r];
    }
    if (idx < HID * VOCAB) {
        int k = idx >> 8;
        int c = idx & 255;
        g_fcwt[k * VOCAB + c] = fc_W[c * HID + k];
    }
    if (idx < 16 * BAR_STRIDE) g_bar[idx] = 0u;
    if (idx < BAR_STRIDE)      g_ticket[idx] = 0u;
}

// =====================================================================
// Shared-memory union: LSTM view / FC-tile view (both < 48 KB static)
// =====================================================================
#define FC_WPAD 260
union SMemU {
    struct {
        float sh_h[4][8 * CH];     // h(t-1): [batch][chunk*CH + j]
        int   sh_tok[2][4];        // double-buffered tokens
    } l;
    struct {
        float w[32][FC_WPAD];      // weight k-slab  (~33 KB)
        float h[32][33];           // h rows k-slab  (~4.2 KB)
    } f;
};

// =====================================================================
// FC tile: 32 rows x 256 cols, 256 threads, 4x8 register tile, f32x2.
// In-place over the hs region (reads all k-slabs before storing).
// =====================================================================
__device__ __forceinline__ void fc_tile(float* __restrict__ sw,   // [32][FC_WPAD]
                                        float* __restrict__ shh,  // [32][33]
                                        float* __restrict__ out,
                                        const float* __restrict__ fc_b,
                                        size_t row_base, int tid) {
    const int rg = tid >> 5;          // 0..7 -> rows rg*4 .. +4
    const int cg = tid & 31;          // cols cg*8 .. +8

    unsigned long long acc[4][4];
#pragma unroll
    for (int a = 0; a < 4; a++)
#pragma unroll
        for (int b = 0; b < 4; b++) acc[a][b] = 0ull;

    for (int k0 = 0; k0 < HID; k0 += 32) {
        __syncthreads();              // also joins the tid0 dependency spin
        for (int i = tid; i < 32 * 64; i += 256) {
            int kk = i >> 6, c4 = i & 63;
            *reinterpret_cast<float4*>(&sw[kk * FC_WPAD + c4 * 4]) =
                *reinterpret_cast<const float4*>(&g_fcwt[(size_t)(k0 + kk) * VOCAB + c4 * 4]);
        }
        {
            int rr = tid >> 3, k4 = tid & 7;
            float4 v = *reinterpret_cast<const float4*>(
                &out[(row_base + rr) * HID + k0 + k4 * 4]);
            shh[rr * 33 + k4 * 4 + 0] = v.x;
            shh[rr * 33 + k4 * 4 + 1] = v.y;
            shh[rr * 33 + k4 * 4 + 2] = v.z;
            shh[rr * 33 + k4 * 4 + 3] = v.w;
        }
        __syncthreads();
#pragma unroll 4
        for (int kk = 0; kk < 32; kk++) {
            ulonglong2 wv0 = *reinterpret_cast<const ulonglong2*>(&sw[kk * FC_WPAD + cg * 8]);
            ulonglong2 wv1 = *reinterpret_cast<const ulonglong2*>(&sw[kk * FC_WPAD + cg * 8 + 4]);
#pragma unroll
            for (int rr = 0; rr < 4; rr++) {
                float hv = shh[(rg * 4 + rr) * 33 + kk];
                unsigned long long hp = pk2(hv, hv);
                ffma2(acc[rr][0], hp, wv0.x);
                ffma2(acc[rr][1], hp, wv0.y);
                ffma2(acc[rr][2], hp, wv1.x);
                ffma2(acc[rr][3], hp, wv1.y);
            }
        }
    }

    float bias[8];
#pragma unroll
    for (int cc = 0; cc < 8; cc++) bias[cc] = __ldg(&fc_b[cg * 8 + cc]);
#pragma unroll
    for (int rr = 0; rr < 4; rr++) {
        float v[8];
        upk2(acc[rr][0], v[0], v[1]);
        upk2(acc[rr][1], v[2], v[3]);
        upk2(acc[rr][2], v[4], v[5]);
        upk2(acc[rr][3], v[6], v[7]);
        float4 o0 = make_float4(v[0] + bias[0], v[1] + bias[1], v[2] + bias[2], v[3] + bias[3]);
        float4 o1 = make_float4(v[4] + bias[4], v[5] + bias[5], v[6] + bias[6], v[7] + bias[7]);
        float* dst = out + (row_base + rg * 4 + rr) * VOCAB + cg * 8;
        *reinterpret_cast<float4*>(dst)     = o0;
        *reinterpret_cast<float4*>(dst + 4) = o1;
    }
}

// =====================================================================
// Fused kernel, grid 148 (1 CTA/SM):
//   CTA 0..127 : persistent LSTM (proven R11 path), then join FC pool.
//   CTA 128..147: FC workers from t=0 on the 20 LSTM-free SMs.
// Barrier: per-group padded counter (one per 256-B line -> own L2
// slice); 8 red.release arrivals + ONE tid0 poller per group per step.
// =====================================================================
__global__ void __launch_bounds__(256, 1)
fused_kernel(const int* __restrict__ x,
             const float* __restrict__ W_hh,
             float* __restrict__ out,
             const float* __restrict__ fc_b) {
    __shared__ SMemU sm;
    __shared__ unsigned sh_tix;

    const int cta = blockIdx.x;
    const int tid = threadIdx.x;
    float* hsout = out;                                 // [B][T][H]

    if (cta < 128) {
        // ================= LSTM phase (proven structure) =================
        const int gb     = cta >> 3;       // batch group 0..15
        const int m      = cta & 7;        // gate-slice member 0..7
        const int b_base = gb * 4;
        const int j_base = m * 32;

        const int j   = tid >> 3;          // local column 0..31
        const int kq  = tid & 7;           // k-chunk 0..7 (32 k each)
        const int bmy = kq >> 1;           // epilogue batch owned by this thread
        const int row0 = j_base + j;       // gate-0 row; gate g at row0 + g*256

        unsigned long long w2[64];
#pragma unroll
        for (int g = 0; g < 4; g++) {
            const float4* wr = reinterpret_cast<const float4*>(
                W_hh + (size_t)(g * 256 + row0) * HID + kq * 32);
#pragma unroll
            for (int i = 0; i < 8; i++) {
                float4 v = wr[i];
                w2[g * 16 + 2 * i]     = pk2(v.x, v.y);
                w2[g * 16 + 2 * i + 1] = pk2(v.z, v.w);
            }
        }
        float creg = 0.0f;
        if (tid < 4) sm.l.sh_tok[0][tid] = x[(size_t)(b_base + tid) * T_SEQ + 0] & 255;

        float* hN = out + (size_t)LOGITS_ELEMS;
        float* cN = hN + BATCH * HID;
        unsigned int* bar = &g_bar[gb * BAR_STRIDE];

        for (int t = 0; t < T_SEQ; t++) {
            const int pb = t & 1;

            // stage h(t-1) into skewed smem (L2-only loads)
            {
                int bb = tid >> 6, k4 = tid & 63;
                float4 hv;
                if (t == 0) {
                    hv = make_float4(0.f, 0.f, 0.f, 0.f);
                } else {
                    hv = ldcg4(&hsout[((size_t)(b_base + bb) * T_SEQ + (t - 1)) * HID + k4 * 4]);
                }
                *reinterpret_cast<float4*>(&sm.l.sh_h[bb][(k4 >> 3) * CH + (k4 & 7) * 4]) = hv;
            }
            if (tid < 4 && t + 1 < T_SEQ)
                sm.l.sh_tok[pb ^ 1][tid] = x[(size_t)(b_base + tid) * T_SEQ + t + 1] & 255;
            __syncthreads();

            // token-table contributions (early issue)
            const int tok = sm.l.sh_tok[pb][bmy];
            float xg[4];
#pragma unroll
            for (int g = 0; g < 4; g++)
                xg[g] = __ldg(&g_xtab[tok * G4 + g * 256 + row0]);

            // matmul: 4 gates x 4 batches x 32 k, weights in registers
            unsigned long long acc2[4][4];
#pragma unroll
            for (int g = 0; g < 4; g++)
#pragma unroll
                for (int b = 0; b < 4; b++) acc2[g][b] = 0ull;
#pragma unroll
            for (int b = 0; b < 4; b++) {
                const ulonglong2* hp =
                    reinterpret_cast<const ulonglong2*>(&sm.l.sh_h[b][kq * CH]);
#pragma unroll
                for (int i = 0; i < 8; i++) {
                    ulonglong2 hv = hp[i];
#pragma unroll
                    for (int g = 0; g < 4; g++) {
                        ffma2(acc2[g][b], w2[g * 16 + 2 * i],     hv.x);
                        ffma2(acc2[g][b], w2[g * 16 + 2 * i + 1], hv.y);
                    }
                }
            }

            // horizontal sums
            float af[4][4];
#pragma unroll
            for (int g = 0; g < 4; g++)
#pragma unroll
                for (int b = 0; b < 4; b++) {
                    float a0, a1;
                    upk2(acc2[g][b], a0, a1);
                    af[g][b] = a0 + a1;
                }

            // reduce-scatter over the 8 k-chunks
            const bool lo = (kq < 4);
            float a2[4][2];
#pragma unroll
            for (int g = 0; g < 4; g++) {
                float s0 = lo ? af[g][2] : af[g][0];
                float s1 = lo ? af[g][3] : af[g][1];
                s0 = __shfl_xor_sync(0xffffffffu, s0, 4);
                s1 = __shfl_xor_sync(0xffffffffu, s1, 4);
                a2[g][0] = (lo ? af[g][0] : af[g][2]) + s0;
                a2[g][1] = (lo ? af[g][1] : af[g][3]) + s1;
            }
            const bool sel = (kq & 2);
            float fin[4];
#pragma unroll
            for (int g = 0; g < 4; g++) {
                float s = sel ? a2[g][0] : a2[g][1];
                s = __shfl_xor_sync(0xffffffffu, s, 2);
                fin[g] = (sel ? a2[g][1] : a2[g][0]) + s;
            }
#pragma unroll
            for (int g = 0; g < 4; g++)
                fin[g] += __shfl_xor_sync(0xffffffffu, fin[g], 1);

            // epilogue inline (pair-redundant; odd lane stores)
            {
                float iv = fin[0] + xg[0];
                float fv = fin[1] + xg[1];
                float gv = fin[2] + xg[2];
                float ov = fin[3] + xg[3];
                float is = __fdividef(1.f, 1.f + __expf(-iv));
                float fs = __fdividef(1.f, 1.f + __expf(-fv));
                float gt = 1.f - __fdividef(2.f, 1.f + __expf(2.f * gv));
                float os = __fdividef(1.f, 1.f + __expf(-ov));
                creg = fs * creg + is * gt;
                float ct = 1.f - __fdividef(2.f, 1.f + __expf(2.f * creg));
                float hv = os * ct;
                if (kq & 1) {
                    hsout[((size_t)(b_base + bmy) * T_SEQ + t) * HID + row0] = hv;
                    if (t == T_SEQ - 1) {
                        hN[(b_base + bmy) * HID + row0] = hv;
                        cN[(b_base + bmy) * HID + row0] = creg;
                    }
                }
            }

            // group barrier (proven: 8 releases, ONE poller)
            if (t + 1 < T_SEQ) {
                __syncthreads();
                if (tid == 0) {
                    red_release_add(bar, 1u);
                    const unsigned int target = 8u * (unsigned int)(t + 1);
                    while (ld_acquire(bar) < target) { }
                }
                __syncthreads();
            }
        }
        // final release so counters reach 8*2048 (consumed by FC deps)
        __syncthreads();
        if (tid == 0) red_release_add(bar, 1u);
    }

    // ================= FC worker pool (all 148 CTAs end up here) =========
    for (;;) {
        __syncthreads();                       // protect sh_tix + smem reuse
        if (tid == 0) sh_tix = atomicAdd(&g_ticket[0], 1u);
        __syncthreads();
        unsigned tix = sh_tix;
        if (tix >= N_TILES) break;
        int tc = (int)(tix >> 6);              // t-chunk 0..63 (time-major order)
        int b  = (int)(tix & 63u);             // batch 0..63
        // WAR-safe dep: group completed step 32*tc+32 (its staging already
        // consumed row 32*tc+31). Counter is 8*(steps completed).
        unsigned need = 8u * (32u * (unsigned)tc + 33u);
        if (need > 8u * (unsigned)T_SEQ) need = 8u * (unsigned)T_SEQ;
        if (tid == 0) {
            while (ld_acquire(&g_bar[(b >> 2) * BAR_STRIDE]) < need) { }
        }
        // fc_tile's first __syncthreads joins the spin before any h load
        fc_tile(&sm.f.w[0][0], &sm.f.h[0][0], out, fc_b,
                (size_t)b * T_SEQ + (size_t)(32 * tc), tid);
    }
}

// =====================================================================
extern "C" void kernel_launch(void* const* d_in, const int* in_sizes, int n_in,
                              void* d_out, int out_size) {
    (void)in_sizes; (void)n_in; (void)out_size;
    const int*   x      = (const int*)d_in[0];     // int32 tokens
    const float* W_ih   = (const float*)d_in[1];
    const float* W_hh   = (const float*)d_in[2];
    const float* b_ih   = (const float*)d_in[3];
    const float* b_hh   = (const float*)d_in[4];
    const float* fc_W   = (const float*)d_in[5];
    const float* fc_b   = (const float*)d_in[6];
    float* out = (float*)d_out;

    prep_kernel<<<1024, 256>>>(W_ih, b_ih, b_hh, fc_W);
    fused_kernel<<<148, 256>>>(x, W_hh, out, fc_b);
}